// round 16
// baseline (speedup 1.0000x reference)
#include <cuda_runtime.h>
#include <cuda_fp16.h>
#include <cstdint>

#define VOCAB 32000
#define EMBD  1024
#define HID   1024
#define BATCH 16
#define SEQ   512
#define NTOK  (BATCH*SEQ)
#define NTILE_N (VOCAB/128)      // 250
#define NTICK_P0 512             // pre0 tiles: 4 time-blocks x (16 b x 8 ny)
#define NTILES2 (NTILE_N*32)     // 8000 fc tiles (BM=256)
#define NTICKETS (NTICK_P0 + NTILES2)

__device__ __half g_x   [(size_t)NTOK*EMBD];
__device__ float  g_pre [(size_t)NTOK*HID];
__device__ __half g_hall0[(size_t)SEQ*BATCH*HID];
__device__ __half g_hall1[(size_t)SEQ*BATCH*HID];
__device__ __half g_Wih0h[(size_t)HID*EMBD];
__device__ __half g_Whh0h[(size_t)HID*HID];
__device__ __half g_Wih1h[(size_t)HID*HID];
__device__ __half g_Whh1h[(size_t)HID*HID];
__device__ __half g_fcwh [(size_t)VOCAB*HID];
__device__ float  g_b0[HID];
__device__ float  g_b1[HID];
// per-CTA progress flags: flag[j*32] = number of steps CTA j has completed
__device__ unsigned g_flag0[32*32];
__device__ unsigned g_flag1[32*32];
__device__ unsigned g_cntq[4];
__device__ unsigned g_ticket;

__device__ __forceinline__ uint32_t smem_u32(const void* p){
    return (uint32_t)__cvta_generic_to_shared(p);
}
__device__ __forceinline__ void ldsm_x4(uint32_t &r0,uint32_t &r1,uint32_t &r2,uint32_t &r3,uint32_t a){
    asm volatile("ldmatrix.sync.aligned.m8n8.x4.shared.b16 {%0,%1,%2,%3}, [%4];"
        : "=r"(r0),"=r"(r1),"=r"(r2),"=r"(r3) : "r"(a));
}
__device__ __forceinline__ void ldsm_x2(uint32_t &r0,uint32_t &r1,uint32_t a){
    asm volatile("ldmatrix.sync.aligned.m8n8.x2.shared.b16 {%0,%1}, [%2];"
        : "=r"(r0),"=r"(r1) : "r"(a));
}
__device__ __forceinline__ void mma16816(float c[4], const uint32_t a[4], const uint32_t b[2]){
    asm volatile(
      "mma.sync.aligned.m16n8k16.row.col.f32.f16.f16.f32 "
      "{%0,%1,%2,%3}, {%4,%5,%6,%7}, {%8,%9}, {%0,%1,%2,%3};"
      : "+f"(c[0]), "+f"(c[1]), "+f"(c[2]), "+f"(c[3])
      : "r"(a[0]), "r"(a[1]), "r"(a[2]), "r"(a[3]), "r"(b[0]), "r"(b[1]));
}
__device__ __forceinline__ void cp_async16(void* s, const void* g){
    asm volatile("cp.async.cg.shared.global [%0], [%1], 16;" :: "r"(smem_u32(s)), "l"(g));
}
#define CP_COMMIT() asm volatile("cp.async.commit_group;")
#define CP_WAIT0()  asm volatile("cp.async.wait_group 0;")
#define CP_WAIT2()  asm volatile("cp.async.wait_group 2;")
#define BARX(id)    asm volatile("bar.sync %0, 128;" :: "r"(id) : "memory")

__device__ __forceinline__ unsigned ld_acq(const unsigned* p){
    unsigned v;
    asm volatile("ld.acquire.gpu.global.u32 %0, [%1];" : "=r"(v) : "l"(p) : "memory");
    return v;
}
__device__ __forceinline__ void st_rel(unsigned* p, unsigned v){
    asm volatile("st.release.gpu.global.u32 [%0], %1;" :: "l"(p), "r"(v) : "memory");
}
__device__ __forceinline__ void red_rel(unsigned* p){
    asm volatile("red.release.gpu.global.add.u32 [%0], 1;" :: "l"(p) : "memory");
}
// warp-collective: lanes 0..31 poll 32 per-CTA flags in parallel until all >= target
__device__ __forceinline__ void wait_flags(const unsigned* base, unsigned target, int sleep_ns){
    int lane = threadIdx.x & 31;
    const unsigned* p = &base[lane*32];
    unsigned v = ld_acq(p);
    while (!__all_sync(0xffffffffu, v >= target)){
        if (sleep_ns) __nanosleep(sleep_ns);
        if (v < target) v = ld_acq(p);
    }
}

// ---- prep --------------------------------------------------------------------
__global__ void prep_kernel(const float* __restrict__ Wih0, const float* __restrict__ Whh0,
                            const float* __restrict__ bih0, const float* __restrict__ bhh0,
                            const float* __restrict__ Wih1, const float* __restrict__ Whh1,
                            const float* __restrict__ bih1, const float* __restrict__ bhh1,
                            const float* __restrict__ fcw)
{
    size_t gtid = (size_t)blockIdx.x*blockDim.x + threadIdx.x;
    size_t gs   = (size_t)gridDim.x*blockDim.x;
    const size_t NW = (size_t)HID*HID;
    for (size_t i = gtid; i < NW; i += gs){
        g_Wih0h[i] = __float2half(Wih0[i]);
        g_Whh0h[i] = __float2half(Whh0[i]);
        g_Wih1h[i] = __float2half(Wih1[i]);
        g_Whh1h[i] = __float2half(Whh1[i]);
    }
    const size_t NF4 = (size_t)VOCAB*HID/4;
    for (size_t i = gtid; i < NF4; i += gs){
        float4 v = ((const float4*)fcw)[i];
        __half2* dst = (__half2*)&g_fcwh[i*4];
        dst[0] = __floats2half2_rn(v.x, v.y);
        dst[1] = __floats2half2_rn(v.z, v.w);
    }
    for (size_t i = gtid; i < HID; i += gs){
        g_b0[i] = bih0[i] + bhh0[i];
        g_b1[i] = bih1[i] + bhh1[i];
    }
    for (size_t i = gtid; i < 32*32; i += gs){ g_flag0[i] = 0; g_flag1[i] = 0; }
    if (gtid < 4) g_cntq[gtid] = 0;
    if (gtid == 0) g_ticket = 0;
}

// ---- embedding ----------------------------------------------------------------
__global__ void embed_kernel(const int* __restrict__ ids, const float* __restrict__ emb)
{
    int m = blockIdx.x;
    int row = ids[m];
    const float4* src = (const float4*)(emb + (size_t)row*EMBD);
    __half2* dst = (__half2*)(g_x + (size_t)m*EMBD);
    int t = threadIdx.x;
    float4 v = src[t];
    dst[t*2 + 0] = __floats2half2_rn(v.x, v.y);
    dst[t*2 + 1] = __floats2half2_rn(v.z, v.w);
}

// ---- 128x128 GEMM tile, BK=64, 4-stage, reg frags; cmode 1 = tok->time remap ----
__device__ __forceinline__ void gemm_tile(
    const __half* __restrict__ A, const __half* __restrict__ B,
    const float* __restrict__ bias, float* __restrict__ C,
    int N, int K, int m0, int n0, int cmode, __half* sm)
{
    constexpr int BM=128, BN=128, BK=64, STR=BK+8;
    constexpr int STAGE = (BM+BN)*STR;

    const int tid  = threadIdx.x;
    const int lane = tid & 31, wid = tid >> 5;
    const int wm = (wid & 3)*32, wn = (wid >> 2)*64;

    float acc[2][8][4];
    #pragma unroll
    for (int a=0;a<2;a++) for (int b=0;b<8;b++) for (int c=0;c<4;c++) acc[a][b][c]=0.f;

    auto load_tiles = [&](int s, int k0){
        __half* Ab = sm + s*STAGE;
        __half* Bb = Ab + BM*STR;
        #pragma unroll
        for (int i=0;i<4;i++){
            int c = tid + i*256;
            int r = c >> 3, kc = (c & 7)*8;
            cp_async16(&Ab[r*STR + kc], &A[(size_t)(m0+r)*K + k0 + kc]);
            cp_async16(&Bb[r*STR + kc], &B[(size_t)(n0+r)*K + k0 + kc]);
        }
    };

    uint32_t af[2][2][4], bf[2][8][2];
    auto lf = [&](__half* Ab, __half* Bb, int kk, int pb){
        #pragma unroll
        for (int mi=0; mi<2; mi++){
            int r  = wm + mi*16 + (lane & 15);
            int kc = kk*16 + (lane >> 4)*8;
            ldsm_x4(af[pb][mi][0],af[pb][mi][1],af[pb][mi][2],af[pb][mi][3],
                    smem_u32(&Ab[r*STR + kc]));
        }
        #pragma unroll
        for (int np=0; np<4; np++){
            int gq = lane >> 3;
            int nr = wn + np*16 + (lane & 7) + ((gq >> 1) << 3);
            int kc = kk*16 + ((gq & 1) << 3);
            uint32_t r0,r1,r2,r3;
            ldsm_x4(r0,r1,r2,r3, smem_u32(&Bb[nr*STR + kc]));
            bf[pb][np*2][0]=r0; bf[pb][np*2][1]=r1;
            bf[pb][np*2+1][0]=r2; bf[pb][np*2+1][1]=r3;
        }
    };

    const int KT = K/BK;
    load_tiles(0, 0);     CP_COMMIT();
    load_tiles(1, BK);    CP_COMMIT();
    load_tiles(2, 2*BK);  CP_COMMIT();

    for (int kt = 0; kt < KT; kt++){
        CP_WAIT2();
        __syncthreads();
        if (kt + 3 < KT) load_tiles((kt+3)&3, (kt+3)*BK);
        CP_COMMIT();
        __half* Ab = sm + (kt&3)*STAGE;
        __half* Bb = Ab + BM*STR;
        lf(Ab, Bb, 0, 0);
        #pragma unroll
        for (int kk = 0; kk < 4; kk++){
            if (kk < 3) lf(Ab, Bb, kk+1, (kk+1)&1);
            int pb = kk & 1;
            #pragma unroll
            for (int mi=0; mi<2; mi++)
                #pragma unroll
                for (int ni=0; ni<8; ni++)
                    mma16816(acc[mi][ni], af[pb][mi], bf[pb][ni]);
        }
    }
    CP_WAIT0();

    #pragma unroll
    for (int mi=0; mi<2; mi++){
        #pragma unroll
        for (int ni=0; ni<8; ni++){
            int col = n0 + wn + ni*8 + (lane & 3)*2;
            float bv0 = bias[col], bv1 = bias[col+1];
            #pragma unroll
            for (int h=0; h<2; h++){
                int row = m0 + wm + mi*16 + (lane >> 2) + h*8;
                size_t orow = (cmode == 1) ? (size_t)((row & (SEQ-1))*BATCH + (row >> 9))
                                           : (size_t)row;
                float2 v = make_float2(acc[mi][ni][h*2+0] + bv0,
                                       acc[mi][ni][h*2+1] + bv1);
                *(float2*)&C[orow*(size_t)N + col] = v;
            }
        }
    }
}

// ---- 256x128 fc tile ------------------------------------------------------------
__device__ __forceinline__ void fc_tile256(
    const __half* __restrict__ A, const __half* __restrict__ B,
    const float* __restrict__ bias, float* __restrict__ C,
    int m0, int n0, __half* sm)
{
    constexpr int BM=256, BN=128, BK=64, STR=BK+8;
    constexpr int STAGE = (BM+BN)*STR;

    const int tid  = threadIdx.x;
    const int lane = tid & 31, wid = tid >> 5;
    const int wm = (wid & 3)*64, wn = (wid >> 2)*64;

    float acc[4][8][4];
    #pragma unroll
    for (int a=0;a<4;a++) for (int b=0;b<8;b++) for (int c=0;c<4;c++) acc[a][b][c]=0.f;

    auto load_tiles = [&](int s, int k0){
        __half* Ab = sm + s*STAGE;
        __half* Bb = Ab + BM*STR;
        #pragma unroll
        for (int i=0;i<8;i++){
            int c = tid + i*256;
            int r = c >> 3, kc = (c & 7)*8;
            cp_async16(&Ab[r*STR + kc], &A[(size_t)(m0+r)*HID + k0 + kc]);
        }
        #pragma unroll
        for (int i=0;i<4;i++){
            int c = tid + i*256;
            int r = c >> 3, kc = (c & 7)*8;
            cp_async16(&Bb[r*STR + kc], &B[(size_t)(n0+r)*HID + k0 + kc]);
        }
    };

    uint32_t af[2][4][4], bf[2][8][2];
    auto lf = [&](__half* Ab, __half* Bb, int kk, int pb){
        #pragma unroll
        for (int mi=0; mi<4; mi++){
            int r  = wm + mi*16 + (lane & 15);
            int kc = kk*16 + (lane >> 4)*8;
            ldsm_x4(af[pb][mi][0],af[pb][mi][1],af[pb][mi][2],af[pb][mi][3],
                    smem_u32(&Ab[r*STR + kc]));
        }
        #pragma unroll
        for (int np=0; np<4; np++){
            int gq = lane >> 3;
            int nr = wn + np*16 + (lane & 7) + ((gq >> 1) << 3);
            int kc = kk*16 + ((gq & 1) << 3);
            uint32_t r0,r1,r2,r3;
            ldsm_x4(r0,r1,r2,r3, smem_u32(&Bb[nr*STR + kc]));
            bf[pb][np*2][0]=r0; bf[pb][np*2][1]=r1;
            bf[pb][np*2+1][0]=r2; bf[pb][np*2+1][1]=r3;
        }
    };

    const int KT = HID/BK;
    load_tiles(0, 0);     CP_COMMIT();
    load_tiles(1, BK);    CP_COMMIT();
    load_tiles(2, 2*BK);  CP_COMMIT();

    for (int kt = 0; kt < KT; kt++){
        CP_WAIT2();
        __syncthreads();
        if (kt + 3 < KT) load_tiles((kt+3)&3, (kt+3)*BK);
        CP_COMMIT();
        __half* Ab = sm + (kt&3)*STAGE;
        __half* Bb = Ab + BM*STR;
        lf(Ab, Bb, 0, 0);
        #pragma unroll
        for (int kk = 0; kk < 4; kk++){
            if (kk < 3) lf(Ab, Bb, kk+1, (kk+1)&1);
            int pb = kk & 1;
            #pragma unroll
            for (int mi=0; mi<4; mi++)
                #pragma unroll
                for (int ni=0; ni<8; ni++)
                    mma16816(acc[mi][ni], af[pb][mi], bf[pb][ni]);
        }
    }
    CP_WAIT0();

    #pragma unroll
    for (int mi=0; mi<4; mi++){
        #pragma unroll
        for (int ni=0; ni<8; ni++){
            int col = n0 + wn + ni*8 + (lane & 3)*2;
            float bv0 = bias[col], bv1 = bias[col+1];
            #pragma unroll
            for (int h=0; h<2; h++){
                int row = m0 + wm + mi*16 + (lane >> 2) + h*8;
                size_t orow = (size_t)((row & (BATCH-1))*SEQ + (row >> 4));
                float2 v = make_float2(acc[mi][ni][h*2+0] + bv0,
                                       acc[mi][ni][h*2+1] + bv1);
                *(float2*)&C[orow*(size_t)VOCAB + col] = v;
            }
        }
    }
}

// ---- worker: 512 ungated pre0 tiles first, then 8000 gated fc tiles -------------
__device__ void worker(const float* __restrict__ fcb, float* __restrict__ logits, __half* sm)
{
    __shared__ unsigned s_tk;
    while (true){
        __syncthreads();
        if (threadIdx.x == 0) s_tk = atomicAdd(&g_ticket, 1u);
        __syncthreads();
        unsigned idx = s_tk;
        if (idx >= NTICKETS) return;
        if (idx < NTICK_P0){
            int tb = idx >> 7, j = idx & 127;
            int b = j >> 3, ny = j & 7;
            gemm_tile(g_x, g_Wih0h, g_b0, g_pre, HID, EMBD,
                      (b*4 + tb)*128, ny*128, 1, sm);
            __syncthreads();
            if (threadIdx.x == 0) red_rel(&g_cntq[tb]);
        } else {
            unsigned j = idx - NTICK_P0;
            int ms = j / 2000;
            int r  = j % 2000;
            int ny = r >> 3;
            int mi = ms*8 + (r & 7);
            if (threadIdx.x < 32) wait_flags(g_flag1, (unsigned)(mi*16 + 16), 200);
            __syncthreads();
            fc_tile256(g_hall1, g_fcwh, fcb, logits, mi*256, ny*128, sm);
        }
    }
}

// ---- fused persistent kernel: 148 CTAs ------------------------------------------
__global__ void __launch_bounds__(256,1) rnn_fc_fused(
    const float* __restrict__ pre0, const float* __restrict__ fcb,
    float* __restrict__ logits, float* __restrict__ hid0, float* __restrict__ hid1)
{
    extern __shared__ __align__(16) __half sm[];
    __shared__ float red[2][4][32][4];

    if (blockIdx.x < 64){
        const int tid  = threadIdx.x;
        const int lane = tid & 31, wid = tid >> 5;
        const int layer = blockIdx.x >> 5;
        const int cbi  = blockIdx.x & 31;
        const int cb   = cbi * 32;
        const bool gA  = tid < 128;
        const int nw   = (wid & 3) * 8;

        const int K  = layer ? 2048 : 1024;
        const int SK = K + 8;
        __half* Ws = sm;
        __half* Hs = sm + 32*SK;

        if (layer == 0){
            for (int c = tid; c < 32*128; c += 256){
                int n = c >> 7, q = c & 127;
                *(uint4*)&Ws[n*SK + q*8] = *(const uint4*)&g_Whh0h[(size_t)(cb+n)*HID + q*8];
            }
        } else {
            for (int c = tid; c < 32*128; c += 256){
                int n = c >> 7, q = c & 127;
                *(uint4*)&Ws[n*SK + q*8]        = *(const uint4*)&g_Wih1h[(size_t)(cb+n)*HID + q*8];
                *(uint4*)&Ws[n*SK + 1024 + q*8] = *(const uint4*)&g_Whh1h[(size_t)(cb+n)*HID + q*8];
            }
        }
        __syncthreads();

        const int b1 = lane >> 2, b2 = b1 + 8;
        const int col = cb + nw + (lane & 3)*2;
        float2 bias1 = make_float2(0.f, 0.f);
        if (layer == 1 && gA) bias1 = *(const float2*)&g_b1[col];
        const int KH = K / 32;
        unsigned* myflag = layer ? &g_flag1[cbi*32] : &g_flag0[cbi*32];

        for (int t = 0; t < SEQ; t++){
            // layer0: gate on pre0 time-block availability (once per 128 steps)
            if (layer == 0 && gA && (t & 127) == 0){
                if (tid == 0){
                    while (ld_acq(&g_cntq[t>>7]) < 128) __nanosleep(128);
                }
                BARX(1);
            }

            float2 p1, p2;
            if (layer == 0 && gA){
                p1 = __ldg((const float2*)&pre0[((size_t)t*BATCH + b1)*HID + col]);
                p2 = __ldg((const float2*)&pre0[((size_t)t*BATCH + b2)*HID + col]);
            } else { p1 = bias1; p2 = bias1; }

            float acc[4] = {0.f,0.f,0.f,0.f};
            float ac2[4] = {0.f,0.f,0.f,0.f};
            const bool domA = (layer == 1) || (t > 0);
            const bool domB = (t > 0);

            if (gA){
                if (domA){
                    // parallel flag detect: warp 0, 32 lanes on 32 distinct lines
                    if (wid == 0) wait_flags(g_flag0, layer ? (unsigned)(t+1) : (unsigned)t, 0);
                    BARX(1);
                    if (layer == 0){
                        const __half* hs = &g_hall0[(size_t)(t-1)*BATCH*HID];
                        #pragma unroll
                        for (int i = 0; i < 8; i++){
                            int c = tid + i*128, b = c >> 6, q = c & 63;
                            cp_async16(&Hs[b*SK + q*8], &hs[(size_t)b*HID + q*8]);
                        }
                    } else {
                        const __half* ys = &g_hall0[(size_t)t*BATCH*HID];
                        #pragma unroll
                        for (int i = 0; i < 16; i++){
                            int c = tid + i*128, b = c >> 7, q = c & 127;
                            cp_async16(&Hs[b*SK + q*8], &ys[(size_t)b*HID + q*8]);
                        }
                    }
                    CP_COMMIT(); CP_WAIT0();
                    BARX(1);
                    #pragma unroll 4
                    for (int kt = 0; kt < KH; kt++){
                        uint32_t a[4];
                        ldsm_x4(a[0],a[1],a[2],a[3],
                                smem_u32(&Hs[(lane&15)*SK + kt*16 + (lane>>4)*8]));
                        uint32_t c0,c1;
                        ldsm_x2(c0,c1,
                                smem_u32(&Ws[(nw + (lane&7))*SK + kt*16 + (((lane>>3)&1)<<3)]));
                        uint32_t bv[2] = {c0,c1};
                        if (kt & 1) mma16816(ac2, a, bv);
                        else        mma16816(acc, a, bv);
                    }
                    #pragma unroll
                    for (int i=0;i<4;i++) acc[i] += ac2[i];
                }
            } else {
                if (domB){
                    if (wid == 4) wait_flags(layer ? g_flag1 : g_flag0, (unsigned)t, 0);
                    BARX(2);
                    int tb = tid - 128;
                    if (layer == 0){
                        const __half* hs = &g_hall0[(size_t)(t-1)*BATCH*HID];
                        #pragma unroll
                        for (int i = 0; i < 8; i++){
                            int c = tb + i*128, b = c >> 6, q = c & 63;
                            cp_async16(&Hs[b*SK + 512 + q*8], &hs[(size_t)b*HID + 512 + q*8]);
                        }
                    } else {
                        const __half* hp = &g_hall1[(size_t)(t-1)*BATCH*HID];
                        #pragma unroll
                        for (int i = 0; i < 16; i++){
                            int c = tb + i*128, b = c >> 7, q = c & 127;
                            cp_async16(&Hs[b*SK + 1024 + q*8], &hp[(size_t)b*HID + q*8]);
                        }
                    }
                    CP_COMMIT(); CP_WAIT0();
                    BARX(2);
                    #pragma unroll 4
                    for (int kt = 0; kt < KH; kt++){
                        int kg = KH + kt;
                        uint32_t a[4];
                        ldsm_x4(a[0],a[1],a[2],a[3],
                                smem_u32(&Hs[(lane&15)*SK + kg*16 + (lane>>4)*8]));
                        uint32_t c0,c1;
                        ldsm_x2(c0,c1,
                                smem_u32(&Ws[(nw + (lane&7))*SK + kg*16 + (((lane>>3)&1)<<3)]));
                        uint32_t bv[2] = {c0,c1};
                        if (kt & 1) mma16816(ac2, a, bv);
                        else        mma16816(acc, a, bv);
                    }
                    #pragma unroll
                    for (int i=0;i<4;i++) red[t&1][wid-4][lane][i] = acc[i] + ac2[i];
                }
            }
            __syncthreads();

            if (gA){
                if (domB){
                    #pragma unroll
                    for (int i=0;i<4;i++) acc[i] += red[t&1][wid][lane][i];
                }
                float v0 = tanhf(acc[0] + p1.x), v1 = tanhf(acc[1] + p1.y);
                float v2 = tanhf(acc[2] + p2.x), v3 = tanhf(acc[3] + p2.y);
                __half2 h1 = __floats2half2_rn(v0, v1);
                __half2 h2 = __floats2half2_rn(v2, v3);
                __half* hall = layer ? g_hall1 : g_hall0;
                *(__half2*)&hall[((size_t)t*BATCH + b1)*HID + col] = h1;
                *(__half2*)&hall[((size_t)t*BATCH + b2)*HID + col] = h2;
                if (t == SEQ-1){
                    float* hd = layer ? hid1 : hid0;
                    *(float2*)&hd[b1*HID + col] = make_float2(v0, v1);
                    *(float2*)&hd[b2*HID + col] = make_float2(v2, v3);
                }
                BARX(1);
                if (tid == 0) st_rel(myflag, (unsigned)(t+1));
            }
        }
        __syncthreads();
    }

    worker(fcb, logits, sm);
}

extern "C" void kernel_launch(void* const* d_in, const int* in_sizes, int n_in,
                              void* d_out, int out_size)
{
    const int*   ids  = (const int*)  d_in[0];
    const float* emb  = (const float*)d_in[1];
    const float* Wih0 = (const float*)d_in[2];
    const float* Whh0 = (const float*)d_in[3];
    const float* bih0 = (const float*)d_in[4];
    const float* bhh0 = (const float*)d_in[5];
    const float* Wih1 = (const float*)d_in[6];
    const float* Whh1 = (const float*)d_in[7];
    const float* bih1 = (const float*)d_in[8];
    const float* bhh1 = (const float*)d_in[9];
    const float* fcw  = (const float*)d_in[10];
    const float* fcb  = (const float*)d_in[11];
    float* out = (float*)d_out;

    float *logits = out;
    float *hid0   = out + (size_t)NTOK*VOCAB;
    float *hid1   = hid0 + BATCH*HID;

    float *prep;
    cudaGetSymbolAddress((void**)&prep, g_pre);

    const int FUSED_SMEM = 4*(256+128)*72*2;    // 221184 B
    cudaFuncSetAttribute(rnn_fc_fused, cudaFuncAttributeMaxDynamicSharedMemorySize, FUSED_SMEM);

    prep_kernel<<<1024,256>>>(Wih0,Whh0,bih0,bhh0,Wih1,Whh1,bih1,bhh1,fcw);
    embed_kernel<<<NTOK,256>>>(ids, emb);

    rnn_fc_fused<<<148,256,FUSED_SMEM>>>(prep, fcb, logits, hid0, hid1);
}

// round 17
// speedup vs baseline: 1.1014x; 1.1014x over previous
#include <cuda_runtime.h>
#include <cuda_fp16.h>
#include <cstdint>

#define VOCAB 32000
#define EMBD  1024
#define HID   1024
#define BATCH 16
#define SEQ   512
#define NTOK  (BATCH*SEQ)
#define NTILE_N (VOCAB/128)      // 250
#define NTICK_P0 512             // pre0 tiles first
#define NTICK_W  500             // fcw conversion tickets (64 rows each)
#define NTILES2 (NTILE_N*32)     // 8000 fc tiles (BM=256)
#define NTICKETS (NTICK_P0 + NTICK_W + NTILES2)

__device__ __half g_x   [(size_t)NTOK*EMBD];
__device__ float  g_pre [(size_t)NTOK*HID];
__device__ __half g_hall0[(size_t)SEQ*BATCH*HID];
__device__ __half g_hall1[(size_t)SEQ*BATCH*HID];
__device__ __half g_Wih0h[(size_t)HID*EMBD];
__device__ __half g_Whh0h[(size_t)HID*HID];
__device__ __half g_Wih1h[(size_t)HID*HID];
__device__ __half g_Whh1h[(size_t)HID*HID];
__device__ __half g_fcwh [(size_t)VOCAB*HID];
__device__ float  g_b0[HID];
__device__ float  g_b1[HID];
__device__ unsigned g_cnt0[SEQ];
__device__ unsigned g_cnt1[SEQ];
__device__ unsigned g_cntq[4];
__device__ unsigned g_cntw;
__device__ unsigned g_ticket;

__device__ __forceinline__ uint32_t smem_u32(const void* p){
    return (uint32_t)__cvta_generic_to_shared(p);
}
__device__ __forceinline__ void ldsm_x4(uint32_t &r0,uint32_t &r1,uint32_t &r2,uint32_t &r3,uint32_t a){
    asm volatile("ldmatrix.sync.aligned.m8n8.x4.shared.b16 {%0,%1,%2,%3}, [%4];"
        : "=r"(r0),"=r"(r1),"=r"(r2),"=r"(r3) : "r"(a));
}
__device__ __forceinline__ void ldsm_x2(uint32_t &r0,uint32_t &r1,uint32_t a){
    asm volatile("ldmatrix.sync.aligned.m8n8.x2.shared.b16 {%0,%1}, [%2];"
        : "=r"(r0),"=r"(r1) : "r"(a));
}
__device__ __forceinline__ void mma16816(float c[4], const uint32_t a[4], const uint32_t b[2]){
    asm volatile(
      "mma.sync.aligned.m16n8k16.row.col.f32.f16.f16.f32 "
      "{%0,%1,%2,%3}, {%4,%5,%6,%7}, {%8,%9}, {%0,%1,%2,%3};"
      : "+f"(c[0]), "+f"(c[1]), "+f"(c[2]), "+f"(c[3])
      : "r"(a[0]), "r"(a[1]), "r"(a[2]), "r"(a[3]), "r"(b[0]), "r"(b[1]));
}
__device__ __forceinline__ void cp_async16(void* s, const void* g){
    asm volatile("cp.async.cg.shared.global [%0], [%1], 16;" :: "r"(smem_u32(s)), "l"(g));
}
#define CP_COMMIT() asm volatile("cp.async.commit_group;")
#define CP_WAIT0()  asm volatile("cp.async.wait_group 0;")
#define CP_WAIT2()  asm volatile("cp.async.wait_group 2;")
#define BARX(id)    asm volatile("bar.sync %0, 128;" :: "r"(id) : "memory")

__device__ __forceinline__ unsigned ld_acq(const unsigned* p){
    unsigned v;
    asm volatile("ld.acquire.gpu.global.u32 %0, [%1];" : "=r"(v) : "l"(p) : "memory");
    return v;
}
__device__ __forceinline__ void red_rel(unsigned* p){
    asm volatile("red.release.gpu.global.add.u32 [%0], 1;" :: "l"(p) : "memory");
}

// ---- prep: small weights only (fcw conversion moved to worker tickets) --------
__global__ void prep_kernel(const float* __restrict__ Wih0, const float* __restrict__ Whh0,
                            const float* __restrict__ bih0, const float* __restrict__ bhh0,
                            const float* __restrict__ Wih1, const float* __restrict__ Whh1,
                            const float* __restrict__ bih1, const float* __restrict__ bhh1)
{
    size_t gtid = (size_t)blockIdx.x*blockDim.x + threadIdx.x;
    size_t gs   = (size_t)gridDim.x*blockDim.x;
    const size_t NW4 = (size_t)HID*HID/4;
    for (size_t i = gtid; i < NW4; i += gs){
        float4 a = ((const float4*)Wih0)[i];
        float4 b = ((const float4*)Whh0)[i];
        float4 c = ((const float4*)Wih1)[i];
        float4 d = ((const float4*)Whh1)[i];
        __half2* p;
        p = (__half2*)&g_Wih0h[i*4]; p[0] = __floats2half2_rn(a.x,a.y); p[1] = __floats2half2_rn(a.z,a.w);
        p = (__half2*)&g_Whh0h[i*4]; p[0] = __floats2half2_rn(b.x,b.y); p[1] = __floats2half2_rn(b.z,b.w);
        p = (__half2*)&g_Wih1h[i*4]; p[0] = __floats2half2_rn(c.x,c.y); p[1] = __floats2half2_rn(c.z,c.w);
        p = (__half2*)&g_Whh1h[i*4]; p[0] = __floats2half2_rn(d.x,d.y); p[1] = __floats2half2_rn(d.z,d.w);
    }
    for (size_t i = gtid; i < HID; i += gs){
        g_b0[i] = bih0[i] + bhh0[i];
        g_b1[i] = bih1[i] + bhh1[i];
    }
    for (size_t i = gtid; i < SEQ; i += gs){ g_cnt0[i] = 0; g_cnt1[i] = 0; }
    if (gtid < 4) g_cntq[gtid] = 0;
    if (gtid == 0){ g_ticket = 0; g_cntw = 0; }
}

// ---- embedding ----------------------------------------------------------------
__global__ void embed_kernel(const int* __restrict__ ids, const float* __restrict__ emb)
{
    int m = blockIdx.x;
    int row = ids[m];
    const float4* src = (const float4*)(emb + (size_t)row*EMBD);
    __half2* dst = (__half2*)(g_x + (size_t)m*EMBD);
    int t = threadIdx.x;
    float4 v = src[t];
    dst[t*2 + 0] = __floats2half2_rn(v.x, v.y);
    dst[t*2 + 1] = __floats2half2_rn(v.z, v.w);
}

// ---- 128x128 GEMM tile, BK=64, 4-stage, reg frags; cmode 1 = tok->time remap ----
__device__ __forceinline__ void gemm_tile(
    const __half* __restrict__ A, const __half* __restrict__ B,
    const float* __restrict__ bias, float* __restrict__ C,
    int N, int K, int m0, int n0, int cmode, __half* sm)
{
    constexpr int BM=128, BN=128, BK=64, STR=BK+8;
    constexpr int STAGE = (BM+BN)*STR;

    const int tid  = threadIdx.x;
    const int lane = tid & 31, wid = tid >> 5;
    const int wm = (wid & 3)*32, wn = (wid >> 2)*64;

    float acc[2][8][4];
    #pragma unroll
    for (int a=0;a<2;a++) for (int b=0;b<8;b++) for (int c=0;c<4;c++) acc[a][b][c]=0.f;

    auto load_tiles = [&](int s, int k0){
        __half* Ab = sm + s*STAGE;
        __half* Bb = Ab + BM*STR;
        #pragma unroll
        for (int i=0;i<4;i++){
            int c = tid + i*256;
            int r = c >> 3, kc = (c & 7)*8;
            cp_async16(&Ab[r*STR + kc], &A[(size_t)(m0+r)*K + k0 + kc]);
            cp_async16(&Bb[r*STR + kc], &B[(size_t)(n0+r)*K + k0 + kc]);
        }
    };

    uint32_t af[2][2][4], bf[2][8][2];
    auto lf = [&](__half* Ab, __half* Bb, int kk, int pb){
        #pragma unroll
        for (int mi=0; mi<2; mi++){
            int r  = wm + mi*16 + (lane & 15);
            int kc = kk*16 + (lane >> 4)*8;
            ldsm_x4(af[pb][mi][0],af[pb][mi][1],af[pb][mi][2],af[pb][mi][3],
                    smem_u32(&Ab[r*STR + kc]));
        }
        #pragma unroll
        for (int np=0; np<4; np++){
            int gq = lane >> 3;
            int nr = wn + np*16 + (lane & 7) + ((gq >> 1) << 3);
            int kc = kk*16 + ((gq & 1) << 3);
            uint32_t r0,r1,r2,r3;
            ldsm_x4(r0,r1,r2,r3, smem_u32(&Bb[nr*STR + kc]));
            bf[pb][np*2][0]=r0; bf[pb][np*2][1]=r1;
            bf[pb][np*2+1][0]=r2; bf[pb][np*2+1][1]=r3;
        }
    };

    const int KT = K/BK;
    load_tiles(0, 0);     CP_COMMIT();
    load_tiles(1, BK);    CP_COMMIT();
    load_tiles(2, 2*BK);  CP_COMMIT();

    for (int kt = 0; kt < KT; kt++){
        CP_WAIT2();
        __syncthreads();
        if (kt + 3 < KT) load_tiles((kt+3)&3, (kt+3)*BK);
        CP_COMMIT();
        __half* Ab = sm + (kt&3)*STAGE;
        __half* Bb = Ab + BM*STR;
        lf(Ab, Bb, 0, 0);
        #pragma unroll
        for (int kk = 0; kk < 4; kk++){
            if (kk < 3) lf(Ab, Bb, kk+1, (kk+1)&1);
            int pb = kk & 1;
            #pragma unroll
            for (int mi=0; mi<2; mi++)
                #pragma unroll
                for (int ni=0; ni<8; ni++)
                    mma16816(acc[mi][ni], af[pb][mi], bf[pb][ni]);
        }
    }
    CP_WAIT0();

    #pragma unroll
    for (int mi=0; mi<2; mi++){
        #pragma unroll
        for (int ni=0; ni<8; ni++){
            int col = n0 + wn + ni*8 + (lane & 3)*2;
            float bv0 = bias[col], bv1 = bias[col+1];
            #pragma unroll
            for (int h=0; h<2; h++){
                int row = m0 + wm + mi*16 + (lane >> 2) + h*8;
                size_t orow = (cmode == 1) ? (size_t)((row & (SEQ-1))*BATCH + (row >> 9))
                                           : (size_t)row;
                float2 v = make_float2(acc[mi][ni][h*2+0] + bv0,
                                       acc[mi][ni][h*2+1] + bv1);
                *(float2*)&C[orow*(size_t)N + col] = v;
            }
        }
    }
}

// ---- 256x128 fc tile ------------------------------------------------------------
__device__ __forceinline__ void fc_tile256(
    const __half* __restrict__ A, const __half* __restrict__ B,
    const float* __restrict__ bias, float* __restrict__ C,
    int m0, int n0, __half* sm)
{
    constexpr int BM=256, BN=128, BK=64, STR=BK+8;
    constexpr int STAGE = (BM+BN)*STR;

    const int tid  = threadIdx.x;
    const int lane = tid & 31, wid = tid >> 5;
    const int wm = (wid & 3)*64, wn = (wid >> 2)*64;

    float acc[4][8][4];
    #pragma unroll
    for (int a=0;a<4;a++) for (int b=0;b<8;b++) for (int c=0;c<4;c++) acc[a][b][c]=0.f;

    auto load_tiles = [&](int s, int k0){
        __half* Ab = sm + s*STAGE;
        __half* Bb = Ab + BM*STR;
        #pragma unroll
        for (int i=0;i<8;i++){
            int c = tid + i*256;
            int r = c >> 3, kc = (c & 7)*8;
            cp_async16(&Ab[r*STR + kc], &A[(size_t)(m0+r)*HID + k0 + kc]);
        }
        #pragma unroll
        for (int i=0;i<4;i++){
            int c = tid + i*256;
            int r = c >> 3, kc = (c & 7)*8;
            cp_async16(&Bb[r*STR + kc], &B[(size_t)(n0+r)*HID + k0 + kc]);
        }
    };

    uint32_t af[2][4][4], bf[2][8][2];
    auto lf = [&](__half* Ab, __half* Bb, int kk, int pb){
        #pragma unroll
        for (int mi=0; mi<4; mi++){
            int r  = wm + mi*16 + (lane & 15);
            int kc = kk*16 + (lane >> 4)*8;
            ldsm_x4(af[pb][mi][0],af[pb][mi][1],af[pb][mi][2],af[pb][mi][3],
                    smem_u32(&Ab[r*STR + kc]));
        }
        #pragma unroll
        for (int np=0; np<4; np++){
            int gq = lane >> 3;
            int nr = wn + np*16 + (lane & 7) + ((gq >> 1) << 3);
            int kc = kk*16 + ((gq & 1) << 3);
            uint32_t r0,r1,r2,r3;
            ldsm_x4(r0,r1,r2,r3, smem_u32(&Bb[nr*STR + kc]));
            bf[pb][np*2][0]=r0; bf[pb][np*2][1]=r1;
            bf[pb][np*2+1][0]=r2; bf[pb][np*2+1][1]=r3;
        }
    };

    const int KT = HID/BK;
    load_tiles(0, 0);     CP_COMMIT();
    load_tiles(1, BK);    CP_COMMIT();
    load_tiles(2, 2*BK);  CP_COMMIT();

    for (int kt = 0; kt < KT; kt++){
        CP_WAIT2();
        __syncthreads();
        if (kt + 3 < KT) load_tiles((kt+3)&3, (kt+3)*BK);
        CP_COMMIT();
        __half* Ab = sm + (kt&3)*STAGE;
        __half* Bb = Ab + BM*STR;
        lf(Ab, Bb, 0, 0);
        #pragma unroll
        for (int kk = 0; kk < 4; kk++){
            if (kk < 3) lf(Ab, Bb, kk+1, (kk+1)&1);
            int pb = kk & 1;
            #pragma unroll
            for (int mi=0; mi<4; mi++)
                #pragma unroll
                for (int ni=0; ni<8; ni++)
                    mma16816(acc[mi][ni], af[pb][mi], bf[pb][ni]);
        }
    }
    CP_WAIT0();

    #pragma unroll
    for (int mi=0; mi<4; mi++){
        #pragma unroll
        for (int ni=0; ni<8; ni++){
            int col = n0 + wn + ni*8 + (lane & 3)*2;
            float bv0 = bias[col], bv1 = bias[col+1];
            #pragma unroll
            for (int h=0; h<2; h++){
                int row = m0 + wm + mi*16 + (lane >> 2) + h*8;
                size_t orow = (size_t)((row & (BATCH-1))*SEQ + (row >> 4));
                float2 v = make_float2(acc[mi][ni][h*2+0] + bv0,
                                       acc[mi][ni][h*2+1] + bv1);
                *(float2*)&C[orow*(size_t)VOCAB + col] = v;
            }
        }
    }
}

// ---- worker: pre0 tiles -> fcw conversion -> gated fc tiles ---------------------
__device__ void worker(const float* __restrict__ fcw, const float* __restrict__ fcb,
                       float* __restrict__ logits, __half* sm)
{
    __shared__ unsigned s_tk;
    while (true){
        __syncthreads();
        if (threadIdx.x == 0) s_tk = atomicAdd(&g_ticket, 1u);
        __syncthreads();
        unsigned idx = s_tk;
        if (idx >= NTICKETS) return;
        if (idx < NTICK_P0){
            int tb = idx >> 7, j = idx & 127;
            int b = j >> 3, ny = j & 7;
            gemm_tile(g_x, g_Wih0h, g_b0, g_pre, HID, EMBD,
                      (b*4 + tb)*128, ny*128, 1, sm);
            __syncthreads();
            if (threadIdx.x == 0) red_rel(&g_cntq[tb]);
        } else if (idx < NTICK_P0 + NTICK_W){
            // convert 64 rows of fcw (64*1024 floats) to fp16
            size_t base = (size_t)(idx - NTICK_P0) * 64 * HID;
            const float4* src = (const float4*)(fcw + base);
            #pragma unroll 4
            for (int i = threadIdx.x; i < 64*HID/4; i += 256){
                float4 v = src[i];
                __half2* dst = (__half2*)&g_fcwh[base + (size_t)i*4];
                dst[0] = __floats2half2_rn(v.x, v.y);
                dst[1] = __floats2half2_rn(v.z, v.w);
            }
            __syncthreads();
            if (threadIdx.x == 0) red_rel(&g_cntw);
        } else {
            unsigned j = idx - NTICK_P0 - NTICK_W;
            int ms = j / 2000;
            int r  = j % 2000;
            int ny = r >> 3;
            int mi = ms*8 + (r & 7);
            if (threadIdx.x == 0){
                while (ld_acq(&g_cntw) < NTICK_W) __nanosleep(128);
                while (ld_acq(&g_cnt1[mi*16 + 15]) < 32) __nanosleep(128);
            }
            __syncthreads();
            fc_tile256(g_hall1, g_fcwh, fcb, logits, mi*256, ny*128, sm);
        }
    }
}

// ---- fused persistent kernel: 148 CTAs (rnn = exact R15 form) -------------------
__global__ void __launch_bounds__(256,1) rnn_fc_fused(
    const float* __restrict__ pre0, const float* __restrict__ fcw,
    const float* __restrict__ fcb,
    float* __restrict__ logits, float* __restrict__ hid0, float* __restrict__ hid1)
{
    extern __shared__ __align__(16) __half sm[];
    __shared__ float red[2][4][32][4];

    if (blockIdx.x < 64){
        const int tid  = threadIdx.x;
        const int lane = tid & 31, wid = tid >> 5;
        const int layer = blockIdx.x >> 5;
        const int cb   = (blockIdx.x & 31) * 32;
        const bool gA  = tid < 128;
        const int nw   = (wid & 3) * 8;

        const int K  = layer ? 2048 : 1024;
        const int SK = K + 8;
        __half* Ws = sm;
        __half* Hs = sm + 32*SK;

        if (layer == 0){
            for (int c = tid; c < 32*128; c += 256){
                int n = c >> 7, q = c & 127;
                *(uint4*)&Ws[n*SK + q*8] = *(const uint4*)&g_Whh0h[(size_t)(cb+n)*HID + q*8];
            }
        } else {
            for (int c = tid; c < 32*128; c += 256){
                int n = c >> 7, q = c & 127;
                *(uint4*)&Ws[n*SK + q*8]        = *(const uint4*)&g_Wih1h[(size_t)(cb+n)*HID + q*8];
                *(uint4*)&Ws[n*SK + 1024 + q*8] = *(const uint4*)&g_Whh1h[(size_t)(cb+n)*HID + q*8];
            }
        }
        __syncthreads();

        const int b1 = lane >> 2, b2 = b1 + 8;
        const int col = cb + nw + (lane & 3)*2;
        float2 bias1 = make_float2(0.f, 0.f);
        if (layer == 1 && gA) bias1 = *(const float2*)&g_b1[col];
        const int KH = K / 32;

        for (int t = 0; t < SEQ; t++){
            if (layer == 0 && gA && (t & 127) == 0){
                if (tid == 0){
                    while (ld_acq(&g_cntq[t>>7]) < 128) __nanosleep(128);
                }
                BARX(1);
            }

            float2 p1, p2;
            if (layer == 0 && gA){
                p1 = __ldg((const float2*)&pre0[((size_t)t*BATCH + b1)*HID + col]);
                p2 = __ldg((const float2*)&pre0[((size_t)t*BATCH + b2)*HID + col]);
            } else { p1 = bias1; p2 = bias1; }

            float acc[4] = {0.f,0.f,0.f,0.f};
            float ac2[4] = {0.f,0.f,0.f,0.f};
            const bool domA = (layer == 1) || (t > 0);
            const bool domB = (t > 0);

            if (gA){
                if (domA){
                    const unsigned* f = layer ? &g_cnt0[t] : &g_cnt0[t-1];
                    while (ld_acq(f) < 32) {}
                    if (layer == 0){
                        const __half* hs = &g_hall0[(size_t)(t-1)*BATCH*HID];
                        #pragma unroll
                        for (int i = 0; i < 8; i++){
                            int c = tid + i*128, b = c >> 6, q = c & 63;
                            cp_async16(&Hs[b*SK + q*8], &hs[(size_t)b*HID + q*8]);
                        }
                    } else {
                        const __half* ys = &g_hall0[(size_t)t*BATCH*HID];
                        #pragma unroll
                        for (int i = 0; i < 16; i++){
                            int c = tid + i*128, b = c >> 7, q = c & 127;
                            cp_async16(&Hs[b*SK + q*8], &ys[(size_t)b*HID + q*8]);
                        }
                    }
                    CP_COMMIT(); CP_WAIT0();
                    BARX(1);
                    #pragma unroll 4
                    for (int kt = 0; kt < KH; kt++){
                        uint32_t a[4];
                        ldsm_x4(a[0],a[1],a[2],a[3],
                                smem_u32(&Hs[(lane&15)*SK + kt*16 + (lane>>4)*8]));
                        uint32_t c0,c1;
                        ldsm_x2(c0,c1,
                                smem_u32(&Ws[(nw + (lane&7))*SK + kt*16 + (((lane>>3)&1)<<3)]));
                        uint32_t bv[2] = {c0,c1};
                        if (kt & 1) mma16816(ac2, a, bv);
                        else        mma16816(acc, a, bv);
                    }
                    #pragma unroll
                    for (int i=0;i<4;i++) acc[i] += ac2[i];
                }
            } else {
                if (domB){
                    const unsigned* f = layer ? &g_cnt1[t-1] : &g_cnt0[t-1];
                    while (ld_acq(f) < 32) {}
                    int tb = tid - 128;
                    if (layer == 0){
                        const __half* hs = &g_hall0[(size_t)(t-1)*BATCH*HID];
                        #pragma unroll
                        for (int i = 0; i < 8; i++){
                            int c = tb + i*128, b = c >> 6, q = c & 63;
                            cp_async16(&Hs[b*SK + 512 + q*8], &hs[(size_t)b*HID + 512 + q*8]);
                        }
                    } else {
                        const __half* hp = &g_hall1[(size_t)(t-1)*BATCH*HID];
                        #pragma unroll
                        for (int i = 0; i < 16; i++){
                            int c = tb + i*128, b = c >> 7, q = c & 127;
                            cp_async16(&Hs[b*SK + 1024 + q*8], &hp[(size_t)b*HID + q*8]);
                        }
                    }
                    CP_COMMIT(); CP_WAIT0();
                    BARX(2);
                    #pragma unroll 4
                    for (int kt = 0; kt < KH; kt++){
                        int kg = KH + kt;
                        uint32_t a[4];
                        ldsm_x4(a[0],a[1],a[2],a[3],
                                smem_u32(&Hs[(lane&15)*SK + kg*16 + (lane>>4)*8]));
                        uint32_t c0,c1;
                        ldsm_x2(c0,c1,
                                smem_u32(&Ws[(nw + (lane&7))*SK + kg*16 + (((lane>>3)&1)<<3)]));
                        uint32_t bv[2] = {c0,c1};
                        if (kt & 1) mma16816(ac2, a, bv);
                        else        mma16816(acc, a, bv);
                    }
                    #pragma unroll
                    for (int i=0;i<4;i++) red[t&1][wid-4][lane][i] = acc[i] + ac2[i];
                }
            }
            __syncthreads();

            if (gA){
                if (domB){
                    #pragma unroll
                    for (int i=0;i<4;i++) acc[i] += red[t&1][wid][lane][i];
                }
                float v0 = tanhf(acc[0] + p1.x), v1 = tanhf(acc[1] + p1.y);
                float v2 = tanhf(acc[2] + p2.x), v3 = tanhf(acc[3] + p2.y);
                __half2 h1 = __floats2half2_rn(v0, v1);
                __half2 h2 = __floats2half2_rn(v2, v3);
                __half* hall = layer ? g_hall1 : g_hall0;
                *(__half2*)&hall[((size_t)t*BATCH + b1)*HID + col] = h1;
                *(__half2*)&hall[((size_t)t*BATCH + b2)*HID + col] = h2;
                if (t == SEQ-1){
                    float* hd = layer ? hid1 : hid0;
                    *(float2*)&hd[b1*HID + col] = make_float2(v0, v1);
                    *(float2*)&hd[b2*HID + col] = make_float2(v2, v3);
                }
                BARX(1);
                if (tid == 0) red_rel(layer ? &g_cnt1[t] : &g_cnt0[t]);
            }
        }
        __syncthreads();
    }

    worker(fcw, fcb, logits, sm);
}

extern "C" void kernel_launch(void* const* d_in, const int* in_sizes, int n_in,
                              void* d_out, int out_size)
{
    const int*   ids  = (const int*)  d_in[0];
    const float* emb  = (const float*)d_in[1];
    const float* Wih0 = (const float*)d_in[2];
    const float* Whh0 = (const float*)d_in[3];
    const float* bih0 = (const float*)d_in[4];
    const float* bhh0 = (const float*)d_in[5];
    const float* Wih1 = (const float*)d_in[6];
    const float* Whh1 = (const float*)d_in[7];
    const float* bih1 = (const float*)d_in[8];
    const float* bhh1 = (const float*)d_in[9];
    const float* fcw  = (const float*)d_in[10];
    const float* fcb  = (const float*)d_in[11];
    float* out = (float*)d_out;

    float *logits = out;
    float *hid0   = out + (size_t)NTOK*VOCAB;
    float *hid1   = hid0 + BATCH*HID;

    float *prep;
    cudaGetSymbolAddress((void**)&prep, g_pre);

    const int FUSED_SMEM = 4*(256+128)*72*2;    // 221184 B
    cudaFuncSetAttribute(rnn_fc_fused, cudaFuncAttributeMaxDynamicSharedMemorySize, FUSED_SMEM);

    prep_kernel<<<512,256>>>(Wih0,Whh0,bih0,bhh0,Wih1,Whh1,bih1,bhh1);
    embed_kernel<<<NTOK,256>>>(ids, emb);

    rnn_fc_fused<<<148,256,FUSED_SMEM>>>(prep, fcw, fcb, logits, hid0, hid1);
}